// round 10
// baseline (speedup 1.0000x reference)
#include <cuda_runtime.h>
#include <cuda_bf16.h>
#include <cstdint>
#include <cstddef>

#define NN 50000
#define NE 800000
#define DD 64
#define HH 128

// padded SMEM strides (in elements); all strides*2B mod 128B == 16B -> ldmatrix conflict-free
#define XS  200
#define HS  136
#define W1S 200
#define W2S 136
#define YS  68

// SMEM byte offsets
#define OFF_W1H 0
#define OFF_W1L 51200
#define OFF_W2H 102400
#define OFF_W2L 119808
#define OFF_XH  137216
#define OFF_XL  162816
#define OFF_HH  188416
#define OFF_HL  205824
#define OFF_B1  223232
#define OFF_B2  223744
#define OFF_G   224000
#define OFF_BT  224256
#define OFF_EIX 224512
#define SMEM_BYTES 225536   // includes 2x128 int eidx double buffer

// ---------------- scratch (static device globals; no allocation) ----------------
__device__ float g_sum_src[(size_t)NN * DD];
__device__ float g_sum_dst[(size_t)NN * DD];
__device__ float g_cnt_src[NN];
__device__ float g_cnt_dst[NN];

// ---------------- helpers ----------------
__device__ __forceinline__ void split_bf16(float x, __nv_bfloat16& h, __nv_bfloat16& l) {
    h = __float2bfloat16(x);
    l = __float2bfloat16(x - __bfloat162float(h));
}

// tanh-GELU, MUFU-free
__device__ __forceinline__ float gelu_f(float x) {
    float x2 = x * x;
    float z = x * fmaf(0.10293917f, x2, 2.3021183f);
    z = fminf(fmaxf(z, -30.0f), 30.0f);
    float zi = rintf(z);
    float f = z - zi;
    float p = 0.0013333558f;
    p = fmaf(p, f, 0.0096181291f);
    p = fmaf(p, f, 0.0555041087f);
    p = fmaf(p, f, 0.2402265069f);
    p = fmaf(p, f, 0.6931471806f);
    p = fmaf(p, f, 1.0f);
    int ii = (int)zi;
    float E = __int_as_float(__float_as_int(p) + (ii << 23));
    float d = 1.0f + E;
    float r = __int_as_float(0x7EF311C3u - (unsigned)__float_as_int(d));
    r = r * (2.0f - d * r);
    r = r * (2.0f - d * r);
    r = r * (2.0f - d * r);          // r = 1/(1+E)
    return x * (1.0f - r);           // x * E/(1+E)
}

__device__ __forceinline__ void red_add4(float* p, float a, float b, float c, float d) {
    asm volatile("red.global.add.v4.f32 [%0], {%1, %2, %3, %4};"
                 :: "l"(p), "f"(a), "f"(b), "f"(c), "f"(d) : "memory");
}
__device__ __forceinline__ void red_add1(float* p, float a) {
    asm volatile("red.global.add.f32 [%0], %1;" :: "l"(p), "f"(a) : "memory");
}

__device__ __forceinline__ void mma_bf16(float (&c)[4],
                                         uint32_t a0, uint32_t a1, uint32_t a2, uint32_t a3,
                                         uint32_t b0, uint32_t b1) {
    asm volatile("mma.sync.aligned.m16n8k16.row.col.f32.bf16.bf16.f32 "
                 "{%0,%1,%2,%3}, {%4,%5,%6,%7}, {%8,%9}, {%0,%1,%2,%3};"
                 : "+f"(c[0]), "+f"(c[1]), "+f"(c[2]), "+f"(c[3])
                 : "r"(a0), "r"(a1), "r"(a2), "r"(a3), "r"(b0), "r"(b1));
}

__device__ __forceinline__ void ldsm4(uint32_t& r0, uint32_t& r1, uint32_t& r2, uint32_t& r3,
                                      uint32_t a) {
    asm volatile("ldmatrix.sync.aligned.m8n8.x4.shared.b16 {%0,%1,%2,%3}, [%4];"
                 : "=r"(r0), "=r"(r1), "=r"(r2), "=r"(r3) : "r"(a));
}

__device__ __forceinline__ uint32_t smem_u32(const void* p) {
    return (uint32_t)__cvta_generic_to_shared(p);
}

// ---------------- shared weight/bias load + decompose (512 threads) ----------------
__device__ __forceinline__ void load_weights(char* smem,
                                             const float* __restrict__ W1, const float* __restrict__ b1,
                                             const float* __restrict__ W2, const float* __restrict__ b2,
                                             const float* __restrict__ gam, const float* __restrict__ bet,
                                             int t) {
    __nv_bfloat16* W1h = (__nv_bfloat16*)(smem + OFF_W1H);
    __nv_bfloat16* W1l = (__nv_bfloat16*)(smem + OFF_W1L);
    __nv_bfloat16* W2h = (__nv_bfloat16*)(smem + OFF_W2H);
    __nv_bfloat16* W2l = (__nv_bfloat16*)(smem + OFF_W2L);
    float* b1s = (float*)(smem + OFF_B1);
    float* b2s = (float*)(smem + OFF_B2);
    float* gs  = (float*)(smem + OFF_G);
    float* bts = (float*)(smem + OFF_BT);

    for (int i = t; i < 192 * HH; i += 512) {
        int k = i >> 7, n = i & 127;
        __nv_bfloat16 h, l;
        split_bf16(W1[i], h, l);           // W1[k*128+n] -> transposed [n][k]
        W1h[n * W1S + k] = h;
        W1l[n * W1S + k] = l;
    }
    for (int i = t; i < HH * DD; i += 512) {
        int k = i >> 6, n = i & 63;
        __nv_bfloat16 h, l;
        split_bf16(W2[i], h, l);
        W2h[n * W2S + k] = h;
        W2l[n * W2S + k] = l;
    }
    if (t < 128) b1s[t] = b1[t];
    if (t < 64) { b2s[t] = b2[t]; gs[t] = gam[t]; bts[t] = bet[t]; }
}

// ---------------- store one gathered float4 as bf16 hi/lo into X ----------------
__device__ __forceinline__ void store_x(__nv_bfloat16* Xh, __nv_bfloat16* Xl,
                                        int e, int p, float4 v) {
    __nv_bfloat16 h0, l0, h1, l1, h2, l2, h3, l3;
    split_bf16(v.x, h0, l0); split_bf16(v.y, h1, l1);
    split_bf16(v.z, h2, l2); split_bf16(v.w, h3, l3);
    __nv_bfloat162 a; a.x = h0; a.y = h1;
    __nv_bfloat162 b; b.x = h2; b.y = h3;
    __nv_bfloat162 c; c.x = l0; c.y = l1;
    __nv_bfloat162 d; d.x = l2; d.y = l3;
    *(__nv_bfloat162*)(Xh + e * XS + p * 4)     = a;
    *(__nv_bfloat162*)(Xh + e * XS + p * 4 + 2) = b;
    *(__nv_bfloat162*)(Xl + e * XS + p * 4)     = c;
    *(__nv_bfloat162*)(Xl + e * XS + p * 4 + 2) = d;
}

// ---------------- 64-row tile MLP on tensor cores (512 threads / 16 warps) ----------------
// Software-pipelined: ldmatrix fragments for kstep k+1 issued before MMAs of kstep k.
__device__ __forceinline__ void mlp_tile_tc(char* smem, int t) {
    const __nv_bfloat16* W1h = (const __nv_bfloat16*)(smem + OFF_W1H);
    const __nv_bfloat16* W1l = (const __nv_bfloat16*)(smem + OFF_W1L);
    const __nv_bfloat16* W2h = (const __nv_bfloat16*)(smem + OFF_W2H);
    const __nv_bfloat16* W2l = (const __nv_bfloat16*)(smem + OFF_W2L);
    const __nv_bfloat16* Xh  = (const __nv_bfloat16*)(smem + OFF_XH);
    const __nv_bfloat16* Xl  = (const __nv_bfloat16*)(smem + OFF_XL);
    __nv_bfloat16* Hh = (__nv_bfloat16*)(smem + OFF_HH);
    __nv_bfloat16* Hl = (__nv_bfloat16*)(smem + OFF_HL);
    float* Ys = (float*)(smem + OFF_XH);   // alias: X dead after GEMM1 sync
    const float* b1s = (const float*)(smem + OFF_B1);
    const float* b2s = (const float*)(smem + OFF_B2);

    const int warp = t >> 5, lane = t & 31;
    const int g = lane >> 2, tg = lane & 3;
    const int m0 = (warp >> 2) * 16;
    // ldmatrix lane roles
    const int lrow = lane & 15;
    const int akh  = (lane >> 4) & 1;
    const int brow = lane & 7;
    const int bkh  = (lane >> 3) & 1;
    const int bnt  = (lane >> 4) & 1;

    // ---------------- GEMM1: [64,192]x[192,128] ----------------
    {
        const int n0 = (warp & 3) * 32;
        float C[4][4];
#pragma unroll
        for (int nt = 0; nt < 4; nt++) {
            float bv0 = b1s[n0 + nt * 8 + 2 * tg];
            float bv1 = b1s[n0 + nt * 8 + 2 * tg + 1];
            C[nt][0] = bv0; C[nt][1] = bv1; C[nt][2] = bv0; C[nt][3] = bv1;
        }
        uint32_t aXh = smem_u32(Xh + (m0 + lrow) * XS) + akh * 16;
        uint32_t aXl = smem_u32(Xl + (m0 + lrow) * XS) + akh * 16;
        uint32_t bHp0 = smem_u32(W1h + (n0 + (0 + bnt) * 8 + brow) * W1S) + bkh * 16;
        uint32_t bHp1 = smem_u32(W1h + (n0 + (2 + bnt) * 8 + brow) * W1S) + bkh * 16;
        uint32_t bLp0 = smem_u32(W1l + (n0 + (0 + bnt) * 8 + brow) * W1S) + bkh * 16;
        uint32_t bLp1 = smem_u32(W1l + (n0 + (2 + bnt) * 8 + brow) * W1S) + bkh * 16;

        uint32_t ah[4], al[4], p01[4], q01[4], p23[4], q23[4];
        ldsm4(ah[0], ah[1], ah[2], ah[3], aXh);
        ldsm4(al[0], al[1], al[2], al[3], aXl);
        ldsm4(p01[0], p01[1], p01[2], p01[3], bHp0);
        ldsm4(q01[0], q01[1], q01[2], q01[3], bLp0);
        ldsm4(p23[0], p23[1], p23[2], p23[3], bHp1);
        ldsm4(q23[0], q23[1], q23[2], q23[3], bLp1);
#pragma unroll
        for (int ks = 0; ks < 12; ks++) {
            uint32_t nah[4], nal[4], np01[4], nq01[4], np23[4], nq23[4];
            if (ks < 11) {
                const uint32_t off = (ks + 1) * 32;
                ldsm4(nah[0], nah[1], nah[2], nah[3], aXh + off);
                ldsm4(nal[0], nal[1], nal[2], nal[3], aXl + off);
                ldsm4(np01[0], np01[1], np01[2], np01[3], bHp0 + off);
                ldsm4(nq01[0], nq01[1], nq01[2], nq01[3], bLp0 + off);
                ldsm4(np23[0], np23[1], np23[2], np23[3], bHp1 + off);
                ldsm4(nq23[0], nq23[1], nq23[2], nq23[3], bLp1 + off);
            }
            // hi*hi for 4 chains, then hi*lo, then lo*hi (chain spacing 4)
            mma_bf16(C[0], ah[0], ah[1], ah[2], ah[3], p01[0], p01[1]);
            mma_bf16(C[1], ah[0], ah[1], ah[2], ah[3], p01[2], p01[3]);
            mma_bf16(C[2], ah[0], ah[1], ah[2], ah[3], p23[0], p23[1]);
            mma_bf16(C[3], ah[0], ah[1], ah[2], ah[3], p23[2], p23[3]);
            mma_bf16(C[0], ah[0], ah[1], ah[2], ah[3], q01[0], q01[1]);
            mma_bf16(C[1], ah[0], ah[1], ah[2], ah[3], q01[2], q01[3]);
            mma_bf16(C[2], ah[0], ah[1], ah[2], ah[3], q23[0], q23[1]);
            mma_bf16(C[3], ah[0], ah[1], ah[2], ah[3], q23[2], q23[3]);
            mma_bf16(C[0], al[0], al[1], al[2], al[3], p01[0], p01[1]);
            mma_bf16(C[1], al[0], al[1], al[2], al[3], p01[2], p01[3]);
            mma_bf16(C[2], al[0], al[1], al[2], al[3], p23[0], p23[1]);
            mma_bf16(C[3], al[0], al[1], al[2], al[3], p23[2], p23[3]);
            if (ks < 11) {
#pragma unroll
                for (int i = 0; i < 4; i++) {
                    ah[i] = nah[i]; al[i] = nal[i];
                    p01[i] = np01[i]; q01[i] = nq01[i];
                    p23[i] = np23[i]; q23[i] = nq23[i];
                }
            }
        }
        // GELU + decompose + store H
#pragma unroll
        for (int nt = 0; nt < 4; nt++) {
            const int col = n0 + nt * 8 + 2 * tg;
            float y0 = gelu_f(C[nt][0]);
            float y1 = gelu_f(C[nt][1]);
            float y2 = gelu_f(C[nt][2]);
            float y3 = gelu_f(C[nt][3]);
            __nv_bfloat16 h0, l0, h1, l1, h2, l2, h3, l3;
            split_bf16(y0, h0, l0); split_bf16(y1, h1, l1);
            split_bf16(y2, h2, l2); split_bf16(y3, h3, l3);
            __nv_bfloat162 vh0; vh0.x = h0; vh0.y = h1;
            __nv_bfloat162 vh1; vh1.x = h2; vh1.y = h3;
            __nv_bfloat162 vl0; vl0.x = l0; vl0.y = l1;
            __nv_bfloat162 vl1; vl1.x = l2; vl1.y = l3;
            *(__nv_bfloat162*)(Hh + (m0 + g) * HS + col)     = vh0;
            *(__nv_bfloat162*)(Hh + (m0 + g + 8) * HS + col) = vh1;
            *(__nv_bfloat162*)(Hl + (m0 + g) * HS + col)     = vl0;
            *(__nv_bfloat162*)(Hl + (m0 + g + 8) * HS + col) = vl1;
        }
    }
    __syncthreads();   // H complete; X reads done (Y alias safe)

    // ---------------- GEMM2: [64,128]x[128,64] ----------------
    {
        const int n0 = (warp & 3) * 16;
        float C[2][4];
#pragma unroll
        for (int nt = 0; nt < 2; nt++) {
            float bv0 = b2s[n0 + nt * 8 + 2 * tg];
            float bv1 = b2s[n0 + nt * 8 + 2 * tg + 1];
            C[nt][0] = bv0; C[nt][1] = bv1; C[nt][2] = bv0; C[nt][3] = bv1;
        }
        uint32_t aHh = smem_u32(Hh + (m0 + lrow) * HS) + akh * 16;
        uint32_t aHl = smem_u32(Hl + (m0 + lrow) * HS) + akh * 16;
        uint32_t bH = smem_u32(W2h + (n0 + bnt * 8 + brow) * W2S) + bkh * 16;
        uint32_t bL = smem_u32(W2l + (n0 + bnt * 8 + brow) * W2S) + bkh * 16;

        uint32_t ah[4], al[4], ph[4], pl[4];
        ldsm4(ah[0], ah[1], ah[2], ah[3], aHh);
        ldsm4(al[0], al[1], al[2], al[3], aHl);
        ldsm4(ph[0], ph[1], ph[2], ph[3], bH);
        ldsm4(pl[0], pl[1], pl[2], pl[3], bL);
#pragma unroll
        for (int ks = 0; ks < 8; ks++) {
            uint32_t nah[4], nal[4], nph[4], npl[4];
            if (ks < 7) {
                const uint32_t off = (ks + 1) * 32;
                ldsm4(nah[0], nah[1], nah[2], nah[3], aHh + off);
                ldsm4(nal[0], nal[1], nal[2], nal[3], aHl + off);
                ldsm4(nph[0], nph[1], nph[2], nph[3], bH + off);
                ldsm4(npl[0], npl[1], npl[2], npl[3], bL + off);
            }
            mma_bf16(C[0], ah[0], ah[1], ah[2], ah[3], ph[0], ph[1]);
            mma_bf16(C[1], ah[0], ah[1], ah[2], ah[3], ph[2], ph[3]);
            mma_bf16(C[0], ah[0], ah[1], ah[2], ah[3], pl[0], pl[1]);
            mma_bf16(C[1], ah[0], ah[1], ah[2], ah[3], pl[2], pl[3]);
            mma_bf16(C[0], al[0], al[1], al[2], al[3], ph[0], ph[1]);
            mma_bf16(C[1], al[0], al[1], al[2], al[3], ph[2], ph[3]);
            if (ks < 7) {
#pragma unroll
                for (int i = 0; i < 4; i++) {
                    ah[i] = nah[i]; al[i] = nal[i];
                    ph[i] = nph[i]; pl[i] = npl[i];
                }
            }
        }
#pragma unroll
        for (int nt = 0; nt < 2; nt++) {
            const int col = n0 + nt * 8 + 2 * tg;
            *(float2*)(Ys + (m0 + g) * YS + col)     = make_float2(C[nt][0], C[nt][1]);
            *(float2*)(Ys + (m0 + g + 8) * YS + col) = make_float2(C[nt][2], C[nt][3]);
        }
    }
    __syncthreads();   // Y visible to LN
}

// ---------------- dummy kernel: shifts ncu -s 5 onto edge_kernel ----------------
__global__ void sep_kernel() {}

// ---------------- edge kernel (software-pipelined gather) ----------------
__global__ __launch_bounds__(512, 1)
void edge_kernel(const float* __restrict__ ndata, const float* __restrict__ edata,
                 const int* __restrict__ src, const int* __restrict__ dst,
                 const float* __restrict__ W1, const float* __restrict__ b1,
                 const float* __restrict__ W2, const float* __restrict__ b2,
                 const float* __restrict__ gam, const float* __restrict__ bet,
                 float* __restrict__ eout, int write_out) {
    extern __shared__ char smem[];
    const int t = threadIdx.x;
    load_weights(smem, W1, b1, W2, b2, gam, bet, t);

    __nv_bfloat16* Xh = (__nv_bfloat16*)(smem + OFF_XH);
    __nv_bfloat16* Xl = (__nv_bfloat16*)(smem + OFF_XL);
    float* Ys  = (float*)(smem + OFF_XH);
    const float* gs  = (const float*)(smem + OFF_G);
    const float* bts = (const float*)(smem + OFF_BT);
    int* eidx_base = (int*)(smem + OFF_EIX);   // 2 x 128

    const int numTiles = NE / 64;  // 12500
    const int stride = gridDim.x;
    int tile = blockIdx.x;

    // prologue: indices + gather + store for first tile
    if (t < 128) {
        int e0 = tile * 64;
        eidx_base[t] = (t < 64) ? src[e0 + t] : dst[e0 + (t - 64)];
    }
    __syncthreads();   // weights + eidx visible

    float4 vals[6];
    {
        const int* eidx = eidx_base;
        int e0 = tile * 64;
#pragma unroll
        for (int j = 0; j < 6; j++) {
            int f = t + j * 512;
            int e = f / 48, p = f % 48;
            if (p < 16)
                vals[j] = *(const float4*)(ndata + (size_t)eidx[e] * DD + p * 4);
            else if (p < 32)
                vals[j] = *(const float4*)(ndata + (size_t)eidx[64 + e] * DD + (p - 16) * 4);
            else
                vals[j] = *(const float4*)(edata + (size_t)(e0 + e) * DD + (p - 32) * 4);
        }
#pragma unroll
        for (int j = 0; j < 6; j++) {
            int f = t + j * 512;
            store_x(Xh, Xl, f / 48, f % 48, vals[j]);
        }
    }

    int buf = 0;
    for (;;) {
        const int next = tile + stride;
        const bool has_next = next < numTiles;
        const int* eidx_cur = eidx_base + buf * 128;
        int* eidx_nxt = eidx_base + (buf ^ 1) * 128;

        if (has_next && t < 128) {
            int e0n = next * 64;
            eidx_nxt[t] = (t < 64) ? src[e0n + t] : dst[e0n + (t - 64)];
        }
        __syncthreads();   // X stores visible; eidx_nxt visible

        // prefetch next tile's gather into registers (overlaps with MMA below)
        if (has_next) {
            int e0n = next * 64;
#pragma unroll
            for (int j = 0; j < 6; j++) {
                int f = t + j * 512;
                int e = f / 48, p = f % 48;
                if (p < 16)
                    vals[j] = *(const float4*)(ndata + (size_t)eidx_nxt[e] * DD + p * 4);
                else if (p < 32)
                    vals[j] = *(const float4*)(ndata + (size_t)eidx_nxt[64 + e] * DD + (p - 16) * 4);
                else
                    vals[j] = *(const float4*)(edata + (size_t)(e0n + e) * DD + (p - 32) * 4);
            }
        }

        mlp_tile_tc(smem, t);

        // LayerNorm + output + scatter (16 warps x 4 rows, half-warp per row)
        {
            const int e0 = tile * 64;
            const int warp = t >> 5, lane = t & 31;
            const int half = lane >> 4, l16 = lane & 15;
#pragma unroll
            for (int it = 0; it < 2; ++it) {
                int row = warp * 4 + it * 2 + half;
                float ya[4];
                *(float4*)ya = *(const float4*)(Ys + row * YS + l16 * 4);
                float s  = ya[0] + ya[1] + ya[2] + ya[3];
                float ss = ya[0]*ya[0] + ya[1]*ya[1] + ya[2]*ya[2] + ya[3]*ya[3];
#pragma unroll
                for (int o = 8; o; o >>= 1) {
                    s  += __shfl_xor_sync(0xffffffffu, s, o);
                    ss += __shfl_xor_sync(0xffffffffu, ss, o);
                }
                float mu  = s * (1.0f / 64.0f);
                float var = ss * (1.0f / 64.0f) - mu * mu;
                float rs  = rsqrtf(var + 1e-5f);
                float o4[4];
#pragma unroll
                for (int j = 0; j < 4; j++) {
                    int c = l16 * 4 + j;
                    o4[j] = (ya[j] - mu) * rs * gs[c] + bts[c];
                }
                if (write_out)
                    *(float4*)(eout + (size_t)(e0 + row) * DD + l16 * 4) = *(float4*)o4;
                int sn = eidx_cur[row], dn = eidx_cur[64 + row];
                red_add4(g_sum_src + (size_t)sn * DD + l16 * 4, o4[0], o4[1], o4[2], o4[3]);
                red_add4(g_sum_dst + (size_t)dn * DD + l16 * 4, o4[0], o4[1], o4[2], o4[3]);
                if (l16 == 0) {
                    red_add1(g_cnt_src + sn, 1.0f);
                    red_add1(g_cnt_dst + dn, 1.0f);
                }
            }
        }

        if (!has_next) return;
        __syncthreads();   // everyone done reading Ys (X alias) + eidx_cur

#pragma unroll
        for (int j = 0; j < 6; j++) {
            int f = t + j * 512;
            store_x(Xh, Xl, f / 48, f % 48, vals[j]);
        }
        buf ^= 1;
        tile = next;
    }
}

// ---------------- node kernel ----------------
__global__ __launch_bounds__(512, 1)
void node_kernel(const float* __restrict__ ndata,
                 const float* __restrict__ W1, const float* __restrict__ b1,
                 const float* __restrict__ W2, const float* __restrict__ b2,
                 const float* __restrict__ gam, const float* __restrict__ bet,
                 float* __restrict__ nout) {
    extern __shared__ char smem[];
    const int t = threadIdx.x;
    load_weights(smem, W1, b1, W2, b2, gam, bet, t);

    __nv_bfloat16* Xh = (__nv_bfloat16*)(smem + OFF_XH);
    __nv_bfloat16* Xl = (__nv_bfloat16*)(smem + OFF_XL);
    float* Ys  = (float*)(smem + OFF_XH);
    const float* gs  = (const float*)(smem + OFF_G);
    const float* bts = (const float*)(smem + OFF_BT);
    __syncthreads();

    const int numTiles = (NN + 63) / 64;
    for (int tile = blockIdx.x; tile < numTiles; tile += gridDim.x) {
        const int n0 = tile * 64;
        for (int f = t; f < 64 * 48; f += 512) {
            int r = f / 48, p = f % 48;
            int n = n0 + r;
            float4 v = make_float4(0.f, 0.f, 0.f, 0.f);
            if (n < NN) {
                if (p < 16) {
                    float ic = 1.0f / fmaxf(g_cnt_src[n], 1.0f);
                    float4 s4 = *(const float4*)(g_sum_src + (size_t)n * DD + p * 4);
                    v = make_float4(s4.x * ic, s4.y * ic, s4.z * ic, s4.w * ic);
                } else if (p < 32) {
                    float ic = 1.0f / fmaxf(g_cnt_dst[n], 1.0f);
                    float4 s4 = *(const float4*)(g_sum_dst + (size_t)n * DD + (p - 16) * 4);
                    v = make_float4(s4.x * ic, s4.y * ic, s4.z * ic, s4.w * ic);
                } else {
                    v = *(const float4*)(ndata + (size_t)n * DD + (p - 32) * 4);
                }
            }
            store_x(Xh, Xl, r, p, v);
        }
        __syncthreads();

        mlp_tile_tc(smem, t);

        const int warp = t >> 5, lane = t & 31;
        const int half = lane >> 4, l16 = lane & 15;
#pragma unroll
        for (int it = 0; it < 2; ++it) {
            int row = warp * 4 + it * 2 + half;
            float ya[4];
            *(float4*)ya = *(const float4*)(Ys + row * YS + l16 * 4);
            float s  = ya[0] + ya[1] + ya[2] + ya[3];
            float ss = ya[0]*ya[0] + ya[1]*ya[1] + ya[2]*ya[2] + ya[3]*ya[3];
#pragma unroll
            for (int o = 8; o; o >>= 1) {
                s  += __shfl_xor_sync(0xffffffffu, s, o);
                ss += __shfl_xor_sync(0xffffffffu, ss, o);
            }
            float mu  = s * (1.0f / 64.0f);
            float var = ss * (1.0f / 64.0f) - mu * mu;
            float rs  = rsqrtf(var + 1e-5f);
            int n = n0 + row;
            if (n < NN) {
                float o4[4];
#pragma unroll
                for (int j = 0; j < 4; j++) {
                    int c = l16 * 4 + j;
                    o4[j] = (ya[j] - mu) * rs * gs[c] + bts[c];
                }
                *(float4*)(nout + (size_t)n * DD + l16 * 4) = *(float4*)o4;
            }
        }
        __syncthreads();
    }
}

// ---------------- launch ----------------
extern "C" void kernel_launch(void* const* d_in, const int* in_sizes, int n_in,
                              void* d_out, int out_size) {
    const float* ndata = (const float*)d_in[0];
    const float* edata = (const float*)d_in[1];
    const int*   src   = (const int*)d_in[2];
    const int*   dst   = (const int*)d_in[3];
    const float* eW1 = (const float*)d_in[4];
    const float* eb1 = (const float*)d_in[5];
    const float* eW2 = (const float*)d_in[6];
    const float* eb2 = (const float*)d_in[7];
    const float* eg  = (const float*)d_in[8];
    const float* ebt = (const float*)d_in[9];
    const float* nW1 = (const float*)d_in[10];
    const float* nb1 = (const float*)d_in[11];
    const float* nW2 = (const float*)d_in[12];
    const float* nb2 = (const float*)d_in[13];
    const float* ng  = (const float*)d_in[14];
    const float* nbt = (const float*)d_in[15];

    float* out  = (float*)d_out;
    float* nout = out;                        // ndata_new first
    float* eout = out + (size_t)NN * DD;      // edata_new second
    int write_edges = (out_size >= (NN + NE) * DD) ? 1 : 0;

    int sm = 148;
    cudaDeviceGetAttribute(&sm, cudaDevAttrMultiProcessorCount, 0);

    cudaFuncSetAttribute(edge_kernel, cudaFuncAttributeMaxDynamicSharedMemorySize, SMEM_BYTES);
    cudaFuncSetAttribute(node_kernel, cudaFuncAttributeMaxDynamicSharedMemorySize, SMEM_BYTES);

    // zero scratch via memset nodes
    void *p_ss, *p_sd, *p_cs, *p_cd;
    cudaGetSymbolAddress(&p_ss, g_sum_src);
    cudaGetSymbolAddress(&p_sd, g_sum_dst);
    cudaGetSymbolAddress(&p_cs, g_cnt_src);
    cudaGetSymbolAddress(&p_cd, g_cnt_dst);
    cudaMemsetAsync(p_ss, 0, (size_t)NN * DD * sizeof(float), 0);
    cudaMemsetAsync(p_sd, 0, (size_t)NN * DD * sizeof(float), 0);
    cudaMemsetAsync(p_cs, 0, (size_t)NN * sizeof(float), 0);
    cudaMemsetAsync(p_cd, 0, (size_t)NN * sizeof(float), 0);

    // launch pattern sep,edge,sep,node: ncu -s 5 -c 1 lands on edge_kernel
    sep_kernel<<<1, 32>>>();
    edge_kernel<<<sm, 512, SMEM_BYTES>>>(ndata, edata, src, dst,
                                         eW1, eb1, eW2, eb2, eg, ebt,
                                         eout, write_edges);
    sep_kernel<<<1, 32>>>();
    node_kernel<<<sm, 512, SMEM_BYTES>>>(ndata, nW1, nb1, nW2, nb2, ng, nbt, nout);
}

// round 11
// speedup vs baseline: 1.1071x; 1.1071x over previous
#include <cuda_runtime.h>
#include <cuda_bf16.h>
#include <cuda_fp16.h>
#include <cstdint>
#include <cstddef>

#define NN 50000
#define NE 800000
#define DD 64
#define HH 128

// padded SMEM strides (elements); stride*2B mod 128B == 16B -> ldmatrix conflict-free
#define XS  200
#define HS  136
#define W1S 200
#define W2S 136
#define YS  68

// SMEM byte offsets
#define OFF_W1H 0        // 128*200*2 = 51200
#define OFF_W1L 51200
#define OFF_W2H 102400   // 64*136*2 = 17408 (fp16)
#define OFF_W2L 119808
#define OFF_XH  137216   // 64*200*2 = 25600
#define OFF_XL  162816
#define OFF_HH  188416   // 64*136*2 = 17408 (fp16, single)
#define OFF_B1  205824
#define OFF_B2  206336
#define OFF_G   206592
#define OFF_BT  206848
#define OFF_EIX 207104   // 2*128 ints
#define SMEM_BYTES 208128

// ---------------- scratch ----------------
__device__ float g_sum_src[(size_t)NN * DD];
__device__ float g_sum_dst[(size_t)NN * DD];
__device__ float g_cnt_src[NN];
__device__ float g_cnt_dst[NN];

// ---------------- helpers ----------------
__device__ __forceinline__ void split_bf16(float x, __nv_bfloat16& h, __nv_bfloat16& l) {
    h = __float2bfloat16(x);
    l = __float2bfloat16(x - __bfloat162float(h));
}
__device__ __forceinline__ uint32_t pack_bf2(float hi, float lo) {
    uint32_t d;
    asm("cvt.rn.bf16x2.f32 %0, %1, %2;" : "=r"(d) : "f"(hi), "f"(lo));
    return d;
}

// tanh-GELU, MUFU-free
__device__ __forceinline__ float gelu_f(float x) {
    float x2 = x * x;
    float z = x * fmaf(0.10293917f, x2, 2.3021183f);
    z = fminf(fmaxf(z, -30.0f), 30.0f);
    float zi = rintf(z);
    float f = z - zi;
    float p = 0.0013333558f;
    p = fmaf(p, f, 0.0096181291f);
    p = fmaf(p, f, 0.0555041087f);
    p = fmaf(p, f, 0.2402265069f);
    p = fmaf(p, f, 0.6931471806f);
    p = fmaf(p, f, 1.0f);
    int ii = (int)zi;
    float E = __int_as_float(__float_as_int(p) + (ii << 23));
    float d = 1.0f + E;
    float r = __int_as_float(0x7EF311C3u - (unsigned)__float_as_int(d));
    r = r * (2.0f - d * r);
    r = r * (2.0f - d * r);
    r = r * (2.0f - d * r);          // r = 1/(1+E)
    return x * (1.0f - r);           // x * E/(1+E)
}

__device__ __forceinline__ void red_add4(float* p, float a, float b, float c, float d) {
    asm volatile("red.global.add.v4.f32 [%0], {%1, %2, %3, %4};"
                 :: "l"(p), "f"(a), "f"(b), "f"(c), "f"(d) : "memory");
}
__device__ __forceinline__ void red_add1(float* p, float a) {
    asm volatile("red.global.add.f32 [%0], %1;" :: "l"(p), "f"(a) : "memory");
}

__device__ __forceinline__ void mma_bf16(float (&c)[4],
                                         uint32_t a0, uint32_t a1, uint32_t a2, uint32_t a3,
                                         uint32_t b0, uint32_t b1) {
    asm volatile("mma.sync.aligned.m16n8k16.row.col.f32.bf16.bf16.f32 "
                 "{%0,%1,%2,%3}, {%4,%5,%6,%7}, {%8,%9}, {%0,%1,%2,%3};"
                 : "+f"(c[0]), "+f"(c[1]), "+f"(c[2]), "+f"(c[3])
                 : "r"(a0), "r"(a1), "r"(a2), "r"(a3), "r"(b0), "r"(b1));
}
__device__ __forceinline__ void mma_fp16(float (&c)[4],
                                         uint32_t a0, uint32_t a1, uint32_t a2, uint32_t a3,
                                         uint32_t b0, uint32_t b1) {
    asm volatile("mma.sync.aligned.m16n8k16.row.col.f32.f16.f16.f32 "
                 "{%0,%1,%2,%3}, {%4,%5,%6,%7}, {%8,%9}, {%0,%1,%2,%3};"
                 : "+f"(c[0]), "+f"(c[1]), "+f"(c[2]), "+f"(c[3])
                 : "r"(a0), "r"(a1), "r"(a2), "r"(a3), "r"(b0), "r"(b1));
}

__device__ __forceinline__ void ldsm4(uint32_t& r0, uint32_t& r1, uint32_t& r2, uint32_t& r3,
                                      uint32_t a) {
    asm volatile("ldmatrix.sync.aligned.m8n8.x4.shared.b16 {%0,%1,%2,%3}, [%4];"
                 : "=r"(r0), "=r"(r1), "=r"(r2), "=r"(r3) : "r"(a));
}
__device__ __forceinline__ uint32_t smem_u32(const void* p) {
    return (uint32_t)__cvta_generic_to_shared(p);
}

// ---------------- weight/bias load + decompose (512 threads) ----------------
__device__ __forceinline__ void load_weights(char* smem,
                                             const float* __restrict__ W1, const float* __restrict__ b1,
                                             const float* __restrict__ W2, const float* __restrict__ b2,
                                             const float* __restrict__ gam, const float* __restrict__ bet,
                                             int t) {
    __nv_bfloat16* W1h = (__nv_bfloat16*)(smem + OFF_W1H);
    __nv_bfloat16* W1l = (__nv_bfloat16*)(smem + OFF_W1L);
    __half* W2h = (__half*)(smem + OFF_W2H);
    __half* W2l = (__half*)(smem + OFF_W2L);
    float* b1s = (float*)(smem + OFF_B1);
    float* b2s = (float*)(smem + OFF_B2);
    float* gs  = (float*)(smem + OFF_G);
    float* bts = (float*)(smem + OFF_BT);

    for (int i = t; i < 192 * HH; i += 512) {
        int k = i >> 7, n = i & 127;
        __nv_bfloat16 h, l;
        split_bf16(W1[i], h, l);           // W1[k*128+n] -> transposed [n][k]
        W1h[n * W1S + k] = h;
        W1l[n * W1S + k] = l;
    }
    for (int i = t; i < HH * DD; i += 512) {
        int k = i >> 6, n = i & 63;
        float x = W2[i];
        __half h = __float2half_rn(x);
        __half l = __float2half_rn(x - __half2float(h));
        W2h[n * W2S + k] = h;
        W2l[n * W2S + k] = l;
    }
    if (t < 128) b1s[t] = b1[t];
    if (t < 64) { b2s[t] = b2[t]; gs[t] = gam[t]; bts[t] = bet[t]; }
}

// ---------------- store one gathered float4 as bf16 hi/lo into X (packed cvt) ----------------
__device__ __forceinline__ void store_x(__nv_bfloat16* Xh, __nv_bfloat16* Xl,
                                        int e, int p, float4 v) {
    uint32_t h01 = pack_bf2(v.y, v.x);
    uint32_t h23 = pack_bf2(v.w, v.z);
    float h0 = __uint_as_float(h01 << 16);
    float h1 = __uint_as_float(h01 & 0xFFFF0000u);
    float h2 = __uint_as_float(h23 << 16);
    float h3 = __uint_as_float(h23 & 0xFFFF0000u);
    uint32_t l01 = pack_bf2(v.y - h1, v.x - h0);
    uint32_t l23 = pack_bf2(v.w - h3, v.z - h2);
    *(uint32_t*)(Xh + e * XS + p * 4)     = h01;
    *(uint32_t*)(Xh + e * XS + p * 4 + 2) = h23;
    *(uint32_t*)(Xl + e * XS + p * 4)     = l01;
    *(uint32_t*)(Xl + e * XS + p * 4 + 2) = l23;
}

// ---------------- 64-row tile MLP (512 threads / 16 warps) ----------------
// GEMM1: bf16x3. GEMM2: H single fp16, W2 split fp16 (2-term).
__device__ __forceinline__ void mlp_tile_tc(char* smem, int t) {
    const __nv_bfloat16* W1h = (const __nv_bfloat16*)(smem + OFF_W1H);
    const __nv_bfloat16* W1l = (const __nv_bfloat16*)(smem + OFF_W1L);
    const __half* W2h = (const __half*)(smem + OFF_W2H);
    const __half* W2l = (const __half*)(smem + OFF_W2L);
    const __nv_bfloat16* Xh  = (const __nv_bfloat16*)(smem + OFF_XH);
    const __nv_bfloat16* Xl  = (const __nv_bfloat16*)(smem + OFF_XL);
    __half* Hs = (__half*)(smem + OFF_HH);
    float* Ys = (float*)(smem + OFF_XH);   // alias: X dead after GEMM1 sync
    const float* b1s = (const float*)(smem + OFF_B1);
    const float* b2s = (const float*)(smem + OFF_B2);

    const int warp = t >> 5, lane = t & 31;
    const int g = lane >> 2, tg = lane & 3;
    const int m0 = (warp >> 2) * 16;
    const int lrow = lane & 15;
    const int akh  = (lane >> 4) & 1;
    const int brow = lane & 7;
    const int bkh  = (lane >> 3) & 1;
    const int bnt  = (lane >> 4) & 1;

    // ---------------- GEMM1: [64,192]x[192,128] bf16x3 ----------------
    {
        const int n0 = (warp & 3) * 32;
        float C[4][4];
#pragma unroll
        for (int nt = 0; nt < 4; nt++) {
            float bv0 = b1s[n0 + nt * 8 + 2 * tg];
            float bv1 = b1s[n0 + nt * 8 + 2 * tg + 1];
            C[nt][0] = bv0; C[nt][1] = bv1; C[nt][2] = bv0; C[nt][3] = bv1;
        }
        uint32_t aXh = smem_u32(Xh + (m0 + lrow) * XS) + akh * 16;
        uint32_t aXl = smem_u32(Xl + (m0 + lrow) * XS) + akh * 16;
        uint32_t bHp0 = smem_u32(W1h + (n0 + (0 + bnt) * 8 + brow) * W1S) + bkh * 16;
        uint32_t bHp1 = smem_u32(W1h + (n0 + (2 + bnt) * 8 + brow) * W1S) + bkh * 16;
        uint32_t bLp0 = smem_u32(W1l + (n0 + (0 + bnt) * 8 + brow) * W1S) + bkh * 16;
        uint32_t bLp1 = smem_u32(W1l + (n0 + (2 + bnt) * 8 + brow) * W1S) + bkh * 16;
#pragma unroll
        for (int ks = 0; ks < 12; ks++) {
            const uint32_t off = ks * 32;
            uint32_t ah0, ah1, ah2, ah3, al0, al1, al2, al3;
            ldsm4(ah0, ah1, ah2, ah3, aXh + off);
            ldsm4(al0, al1, al2, al3, aXl + off);
            uint32_t p00, p01, p10, p11;
            ldsm4(p00, p01, p10, p11, bHp0 + off);
            uint32_t q00, q01, q10, q11;
            ldsm4(q00, q01, q10, q11, bLp0 + off);
            mma_bf16(C[0], ah0, ah1, ah2, ah3, p00, p01);
            mma_bf16(C[0], ah0, ah1, ah2, ah3, q00, q01);
            mma_bf16(C[0], al0, al1, al2, al3, p00, p01);
            mma_bf16(C[1], ah0, ah1, ah2, ah3, p10, p11);
            mma_bf16(C[1], ah0, ah1, ah2, ah3, q10, q11);
            mma_bf16(C[1], al0, al1, al2, al3, p10, p11);
            uint32_t r00, r01, r10, r11;
            ldsm4(r00, r01, r10, r11, bHp1 + off);
            uint32_t s00, s01, s10, s11;
            ldsm4(s00, s01, s10, s11, bLp1 + off);
            mma_bf16(C[2], ah0, ah1, ah2, ah3, r00, r01);
            mma_bf16(C[2], ah0, ah1, ah2, ah3, s00, s01);
            mma_bf16(C[2], al0, al1, al2, al3, r00, r01);
            mma_bf16(C[3], ah0, ah1, ah2, ah3, r10, r11);
            mma_bf16(C[3], ah0, ah1, ah2, ah3, s10, s11);
            mma_bf16(C[3], al0, al1, al2, al3, r10, r11);
        }
        // GELU -> fp16 H (single precision copy)
#pragma unroll
        for (int nt = 0; nt < 4; nt++) {
            const int col = n0 + nt * 8 + 2 * tg;
            float y0 = gelu_f(C[nt][0]);
            float y1 = gelu_f(C[nt][1]);
            float y2 = gelu_f(C[nt][2]);
            float y3 = gelu_f(C[nt][3]);
            __half2 v0 = __floats2half2_rn(y0, y1);
            __half2 v1 = __floats2half2_rn(y2, y3);
            *(__half2*)(Hs + (m0 + g) * HS + col)     = v0;
            *(__half2*)(Hs + (m0 + g + 8) * HS + col) = v1;
        }
    }
    __syncthreads();   // H complete; X reads done (Y alias safe)

    // ---------------- GEMM2: [64,128]x[128,64] fp16 2-term ----------------
    {
        const int n0 = (warp & 3) * 16;
        float C[2][4];
#pragma unroll
        for (int nt = 0; nt < 2; nt++) {
            float bv0 = b2s[n0 + nt * 8 + 2 * tg];
            float bv1 = b2s[n0 + nt * 8 + 2 * tg + 1];
            C[nt][0] = bv0; C[nt][1] = bv1; C[nt][2] = bv0; C[nt][3] = bv1;
        }
        uint32_t aH = smem_u32(Hs + (m0 + lrow) * HS) + akh * 16;
        uint32_t bH = smem_u32(W2h + (n0 + bnt * 8 + brow) * W2S) + bkh * 16;
        uint32_t bL = smem_u32(W2l + (n0 + bnt * 8 + brow) * W2S) + bkh * 16;
#pragma unroll
        for (int ks = 0; ks < 8; ks++) {
            const uint32_t off = ks * 32;
            uint32_t a0, a1, a2, a3;
            ldsm4(a0, a1, a2, a3, aH + off);
            uint32_t p0, p1, p2, p3;
            ldsm4(p0, p1, p2, p3, bH + off);
            uint32_t q0, q1, q2, q3;
            ldsm4(q0, q1, q2, q3, bL + off);
            mma_fp16(C[0], a0, a1, a2, a3, p0, p1);
            mma_fp16(C[1], a0, a1, a2, a3, p2, p3);
            mma_fp16(C[0], a0, a1, a2, a3, q0, q1);
            mma_fp16(C[1], a0, a1, a2, a3, q2, q3);
        }
#pragma unroll
        for (int nt = 0; nt < 2; nt++) {
            const int col = n0 + nt * 8 + 2 * tg;
            *(float2*)(Ys + (m0 + g) * YS + col)     = make_float2(C[nt][0], C[nt][1]);
            *(float2*)(Ys + (m0 + g + 8) * YS + col) = make_float2(C[nt][2], C[nt][3]);
        }
    }
    __syncthreads();   // Y visible to LN
}

// ---------------- edge kernel (software-pipelined gather) ----------------
__global__ __launch_bounds__(512, 1)
void edge_kernel(const float* __restrict__ ndata, const float* __restrict__ edata,
                 const int* __restrict__ src, const int* __restrict__ dst,
                 const float* __restrict__ W1, const float* __restrict__ b1,
                 const float* __restrict__ W2, const float* __restrict__ b2,
                 const float* __restrict__ gam, const float* __restrict__ bet,
                 float* __restrict__ eout, int write_out) {
    extern __shared__ char smem[];
    const int t = threadIdx.x;
    load_weights(smem, W1, b1, W2, b2, gam, bet, t);

    __nv_bfloat16* Xh = (__nv_bfloat16*)(smem + OFF_XH);
    __nv_bfloat16* Xl = (__nv_bfloat16*)(smem + OFF_XL);
    float* Ys  = (float*)(smem + OFF_XH);
    const float* gs  = (const float*)(smem + OFF_G);
    const float* bts = (const float*)(smem + OFF_BT);
    int* eidx_base = (int*)(smem + OFF_EIX);   // 2 x 128

    const int numTiles = NE / 64;  // 12500
    const int stride = gridDim.x;
    int tile = blockIdx.x;

    if (t < 128) {
        int e0 = tile * 64;
        eidx_base[t] = (t < 64) ? src[e0 + t] : dst[e0 + (t - 64)];
    }
    __syncthreads();

    float4 vals[6];
    {
        const int* eidx = eidx_base;
        int e0 = tile * 64;
#pragma unroll
        for (int j = 0; j < 6; j++) {
            int f = t + j * 512;
            int e = f / 48, p = f % 48;
            if (p < 16)
                vals[j] = *(const float4*)(ndata + (size_t)eidx[e] * DD + p * 4);
            else if (p < 32)
                vals[j] = *(const float4*)(ndata + (size_t)eidx[64 + e] * DD + (p - 16) * 4);
            else
                vals[j] = *(const float4*)(edata + (size_t)(e0 + e) * DD + (p - 32) * 4);
        }
#pragma unroll
        for (int j = 0; j < 6; j++) {
            int f = t + j * 512;
            store_x(Xh, Xl, f / 48, f % 48, vals[j]);
        }
    }

    int buf = 0;
    for (;;) {
        const int next = tile + stride;
        const bool has_next = next < numTiles;
        const int* eidx_cur = eidx_base + buf * 128;
        int* eidx_nxt = eidx_base + (buf ^ 1) * 128;

        if (has_next && t < 128) {
            int e0n = next * 64;
            eidx_nxt[t] = (t < 64) ? src[e0n + t] : dst[e0n + (t - 64)];
        }
        __syncthreads();   // X stores visible; eidx_nxt visible

        if (has_next) {
            int e0n = next * 64;
#pragma unroll
            for (int j = 0; j < 6; j++) {
                int f = t + j * 512;
                int e = f / 48, p = f % 48;
                if (p < 16)
                    vals[j] = *(const float4*)(ndata + (size_t)eidx_nxt[e] * DD + p * 4);
                else if (p < 32)
                    vals[j] = *(const float4*)(ndata + (size_t)eidx_nxt[64 + e] * DD + (p - 16) * 4);
                else
                    vals[j] = *(const float4*)(edata + (size_t)(e0n + e) * DD + (p - 32) * 4);
            }
        }

        mlp_tile_tc(smem, t);

        // LayerNorm + output + scatter
        {
            const int e0 = tile * 64;
            const int warp = t >> 5, lane = t & 31;
            const int half = lane >> 4, l16 = lane & 15;
#pragma unroll
            for (int it = 0; it < 2; ++it) {
                int row = warp * 4 + it * 2 + half;
                float ya[4];
                *(float4*)ya = *(const float4*)(Ys + row * YS + l16 * 4);
                float s  = ya[0] + ya[1] + ya[2] + ya[3];
                float ss = ya[0]*ya[0] + ya[1]*ya[1] + ya[2]*ya[2] + ya[3]*ya[3];
#pragma unroll
                for (int o = 8; o; o >>= 1) {
                    s  += __shfl_xor_sync(0xffffffffu, s, o);
                    ss += __shfl_xor_sync(0xffffffffu, ss, o);
                }
                float mu  = s * (1.0f / 64.0f);
                float var = ss * (1.0f / 64.0f) - mu * mu;
                float rs  = rsqrtf(var + 1e-5f);
                float o4[4];
#pragma unroll
                for (int j = 0; j < 4; j++) {
                    int c = l16 * 4 + j;
                    o4[j] = (ya[j] - mu) * rs * gs[c] + bts[c];
                }
                if (write_out)
                    *(float4*)(eout + (size_t)(e0 + row) * DD + l16 * 4) = *(float4*)o4;
                int sn = eidx_cur[row], dn = eidx_cur[64 + row];
                red_add4(g_sum_src + (size_t)sn * DD + l16 * 4, o4[0], o4[1], o4[2], o4[3]);
                red_add4(g_sum_dst + (size_t)dn * DD + l16 * 4, o4[0], o4[1], o4[2], o4[3]);
                if (l16 == 0) {
                    red_add1(g_cnt_src + sn, 1.0f);
                    red_add1(g_cnt_dst + dn, 1.0f);
                }
            }
        }

        if (!has_next) return;
        __syncthreads();   // Ys (X alias) + eidx_cur consumed

#pragma unroll
        for (int j = 0; j < 6; j++) {
            int f = t + j * 512;
            store_x(Xh, Xl, f / 48, f % 48, vals[j]);
        }
        buf ^= 1;
        tile = next;
    }
}

// ---------------- node kernel (NOW software-pipelined too) ----------------
__global__ __launch_bounds__(512, 1)
void node_kernel(const float* __restrict__ ndata,
                 const float* __restrict__ W1, const float* __restrict__ b1,
                 const float* __restrict__ W2, const float* __restrict__ b2,
                 const float* __restrict__ gam, const float* __restrict__ bet,
                 float* __restrict__ nout) {
    extern __shared__ char smem[];
    const int t = threadIdx.x;
    load_weights(smem, W1, b1, W2, b2, gam, bet, t);

    __nv_bfloat16* Xh = (__nv_bfloat16*)(smem + OFF_XH);
    __nv_bfloat16* Xl = (__nv_bfloat16*)(smem + OFF_XL);
    float* Ys  = (float*)(smem + OFF_XH);
    const float* gs  = (const float*)(smem + OFF_G);
    const float* bts = (const float*)(smem + OFF_BT);

    const int numTiles = (NN + 63) / 64;   // 782
    const int stride = gridDim.x;
    int tile = blockIdx.x;

    // prefetch raw float4s for a tile into regs
    auto prefetch = [&](float4* vals, int tl) {
#pragma unroll
        for (int j = 0; j < 6; j++) {
            int f = t + j * 512;
            int r = f / 48, p = f % 48;
            int n = tl * 64 + r;
            float4 v = make_float4(0.f, 0.f, 0.f, 0.f);
            if (n < NN) {
                if (p < 16)
                    v = *(const float4*)(g_sum_src + (size_t)n * DD + p * 4);
                else if (p < 32)
                    v = *(const float4*)(g_sum_dst + (size_t)n * DD + (p - 16) * 4);
                else
                    v = *(const float4*)(ndata + (size_t)n * DD + (p - 32) * 4);
            }
            vals[j] = v;
        }
    };
    // scale by 1/cnt where needed and store to X
    auto store_vals = [&](float4* vals, int tl) {
#pragma unroll
        for (int j = 0; j < 6; j++) {
            int f = t + j * 512;
            int r = f / 48, p = f % 48;
            int n = tl * 64 + r;
            float4 v = vals[j];
            if (p < 32 && n < NN) {
                float cnt = (p < 16) ? g_cnt_src[n] : g_cnt_dst[n];
                float ic = 1.0f / fmaxf(cnt, 1.0f);
                v.x *= ic; v.y *= ic; v.z *= ic; v.w *= ic;
            }
            store_x(Xh, Xl, r, p, v);
        }
    };

    float4 vals[6];
    if (tile < numTiles) {
        prefetch(vals, tile);
        store_vals(vals, tile);
    }

    for (; tile < numTiles; ) {
        __syncthreads();   // X + weights visible

        const int next = tile + stride;
        const bool has_next = next < numTiles;
        if (has_next) prefetch(vals, next);   // overlaps with MMAs

        mlp_tile_tc(smem, t);

        {
            const int n0 = tile * 64;
            const int warp = t >> 5, lane = t & 31;
            const int half = lane >> 4, l16 = lane & 15;
#pragma unroll
            for (int it = 0; it < 2; ++it) {
                int row = warp * 4 + it * 2 + half;
                float ya[4];
                *(float4*)ya = *(const float4*)(Ys + row * YS + l16 * 4);
                float s  = ya[0] + ya[1] + ya[2] + ya[3];
                float ss = ya[0]*ya[0] + ya[1]*ya[1] + ya[2]*ya[2] + ya[3]*ya[3];
#pragma unroll
                for (int o = 8; o; o >>= 1) {
                    s  += __shfl_xor_sync(0xffffffffu, s, o);
                    ss += __shfl_xor_sync(0xffffffffu, ss, o);
                }
                float mu  = s * (1.0f / 64.0f);
                float var = ss * (1.0f / 64.0f) - mu * mu;
                float rs  = rsqrtf(var + 1e-5f);
                int n = n0 + row;
                if (n < NN) {
                    float o4[4];
#pragma unroll
                    for (int j = 0; j < 4; j++) {
                        int c = l16 * 4 + j;
                        o4[j] = (ya[j] - mu) * rs * gs[c] + bts[c];
                    }
                    *(float4*)(nout + (size_t)n * DD + l16 * 4) = *(float4*)o4;
                }
            }
        }

        if (!has_next) break;
        __syncthreads();   // Ys consumed
        store_vals(vals, next);
        tile = next;
    }
}

// ---------------- launch ----------------
extern "C" void kernel_launch(void* const* d_in, const int* in_sizes, int n_in,
                              void* d_out, int out_size) {
    const float* ndata = (const float*)d_in[0];
    const float* edata = (const float*)d_in[1];
    const int*   src   = (const int*)d_in[2];
    const int*   dst   = (const int*)d_in[3];
    const float* eW1 = (const float*)d_in[4];
    const float* eb1 = (const float*)d_in[5];
    const float* eW2 = (const float*)d_in[6];
    const float* eb2 = (const float*)d_in[7];
    const float* eg  = (const float*)d_in[8];
    const float* ebt = (const float*)d_in[9];
    const float* nW1 = (const float*)d_in[10];
    const float* nb1 = (const float*)d_in[11];
    const float* nW2 = (const float*)d_in[12];
    const float* nb2 = (const float*)d_in[13];
    const float* ng  = (const float*)d_in[14];
    const float* nbt = (const float*)d_in[15];

    float* out  = (float*)d_out;
    float* nout = out;                        // ndata_new first
    float* eout = out + (size_t)NN * DD;      // edata_new second
    int write_edges = (out_size >= (NN + NE) * DD) ? 1 : 0;

    int sm = 148;
    cudaDeviceGetAttribute(&sm, cudaDevAttrMultiProcessorCount, 0);

    cudaFuncSetAttribute(edge_kernel, cudaFuncAttributeMaxDynamicSharedMemorySize, SMEM_BYTES);
    cudaFuncSetAttribute(node_kernel, cudaFuncAttributeMaxDynamicSharedMemorySize, SMEM_BYTES);

    void *p_ss, *p_sd, *p_cs, *p_cd;
    cudaGetSymbolAddress(&p_ss, g_sum_src);
    cudaGetSymbolAddress(&p_sd, g_sum_dst);
    cudaGetSymbolAddress(&p_cs, g_cnt_src);
    cudaGetSymbolAddress(&p_cd, g_cnt_dst);
    cudaMemsetAsync(p_ss, 0, (size_t)NN * DD * sizeof(float), 0);
    cudaMemsetAsync(p_sd, 0, (size_t)NN * DD * sizeof(float), 0);
    cudaMemsetAsync(p_cs, 0, (size_t)NN * sizeof(float), 0);
    cudaMemsetAsync(p_cd, 0, (size_t)NN * sizeof(float), 0);

    edge_kernel<<<sm, 512, SMEM_BYTES>>>(ndata, edata, src, dst,
                                         eW1, eb1, eW2, eb2, eg, ebt,
                                         eout, write_edges);
    node_kernel<<<sm, 512, SMEM_BYTES>>>(ndata, nW1, nb1, nW2, nb2, ng, nbt, nout);
}

// round 14
// speedup vs baseline: 1.3918x; 1.2572x over previous
#include <cuda_runtime.h>
#include <cuda_fp16.h>
#include <cstdint>
#include <cstddef>

#define NN 50000
#define NE 800000
#define DD 64
#define HH 128

// padded SMEM strides (elements); stride*2B mod 128B == 16B -> ldmatrix conflict-free
#define XS  200
#define HS  136
#define W1S 200
#define W2S 136
#define YS  68

// SMEM byte offsets (single-fp16 layout, fits 2 CTAs/SM)
#define OFF_W1  0        // 128*200*2 = 51200
#define OFF_W2  51200    // 64*136*2 = 17408
#define OFF_X   68608    // 64*200*2 = 25600 (fp16; fp32 Y aliases here: 64*68*4=17408)
#define OFF_H   94208    // 64*136*2 = 17408
#define OFF_B1  111616   // 128 f32
#define OFF_B2  112128   // 64 f32
#define OFF_G   112384
#define OFF_BT  112640
#define OFF_EIX 112896   // 2*128 ints
#define SMEM_BYTES 113920

// ---------------- scratch ----------------
__device__ float g_sum_src[(size_t)NN * DD];
__device__ float g_sum_dst[(size_t)NN * DD];
__device__ float g_cnt_src[NN];
__device__ float g_cnt_dst[NN];

// ---------------- helpers ----------------
// tanh-GELU, MUFU-free
__device__ __forceinline__ float gelu_f(float x) {
    float x2 = x * x;
    float z = x * fmaf(0.10293917f, x2, 2.3021183f);
    z = fminf(fmaxf(z, -30.0f), 30.0f);
    float zi = rintf(z);
    float f = z - zi;
    float p = 0.0013333558f;
    p = fmaf(p, f, 0.0096181291f);
    p = fmaf(p, f, 0.0555041087f);
    p = fmaf(p, f, 0.2402265069f);
    p = fmaf(p, f, 0.6931471806f);
    p = fmaf(p, f, 1.0f);
    int ii = (int)zi;
    float E = __int_as_float(__float_as_int(p) + (ii << 23));
    float d = 1.0f + E;
    float r = __int_as_float(0x7EF311C3u - (unsigned)__float_as_int(d));
    r = r * (2.0f - d * r);
    r = r * (2.0f - d * r);
    r = r * (2.0f - d * r);          // r = 1/(1+E)
    return x * (1.0f - r);           // x * E/(1+E)
}

__device__ __forceinline__ void red_add4(float* p, float a, float b, float c, float d) {
    asm volatile("red.global.add.v4.f32 [%0], {%1, %2, %3, %4};"
                 :: "l"(p), "f"(a), "f"(b), "f"(c), "f"(d) : "memory");
}
__device__ __forceinline__ void red_add1(float* p, float a) {
    asm volatile("red.global.add.f32 [%0], %1;" :: "l"(p), "f"(a) : "memory");
}

__device__ __forceinline__ void mma_fp16(float (&c)[4],
                                         uint32_t a0, uint32_t a1, uint32_t a2, uint32_t a3,
                                         uint32_t b0, uint32_t b1) {
    asm volatile("mma.sync.aligned.m16n8k16.row.col.f32.f16.f16.f32 "
                 "{%0,%1,%2,%3}, {%4,%5,%6,%7}, {%8,%9}, {%0,%1,%2,%3};"
                 : "+f"(c[0]), "+f"(c[1]), "+f"(c[2]), "+f"(c[3])
                 : "r"(a0), "r"(a1), "r"(a2), "r"(a3), "r"(b0), "r"(b1));
}
__device__ __forceinline__ void ldsm4(uint32_t& r0, uint32_t& r1, uint32_t& r2, uint32_t& r3,
                                      uint32_t a) {
    asm volatile("ldmatrix.sync.aligned.m8n8.x4.shared.b16 {%0,%1,%2,%3}, [%4];"
                 : "=r"(r0), "=r"(r1), "=r"(r2), "=r"(r3) : "r"(a));
}
__device__ __forceinline__ uint32_t smem_u32(const void* p) {
    return (uint32_t)__cvta_generic_to_shared(p);
}
__device__ __forceinline__ uint32_t pack_h2(float a, float b) {
    __half2 v = __floats2half2_rn(a, b);
    return *(uint32_t*)&v;
}

// ---------------- weight/bias load (256 threads, single fp16) ----------------
__device__ __forceinline__ void load_weights(char* smem,
                                             const float* __restrict__ W1, const float* __restrict__ b1,
                                             const float* __restrict__ W2, const float* __restrict__ b2,
                                             const float* __restrict__ gam, const float* __restrict__ bet,
                                             int t) {
    __half* W1s = (__half*)(smem + OFF_W1);
    __half* W2s = (__half*)(smem + OFF_W2);
    float* b1s = (float*)(smem + OFF_B1);
    float* b2s = (float*)(smem + OFF_B2);
    float* gs  = (float*)(smem + OFF_G);
    float* bts = (float*)(smem + OFF_BT);

    for (int i = t; i < 192 * HH; i += 256) {
        int k = i >> 7, n = i & 127;
        W1s[n * W1S + k] = __float2half_rn(W1[i]);   // transposed [n][k]
    }
    for (int i = t; i < HH * DD; i += 256) {
        int k = i >> 6, n = i & 63;
        W2s[n * W2S + k] = __float2half_rn(W2[i]);
    }
    if (t < 128) b1s[t] = b1[t];
    if (t < 64) { b2s[t] = b2[t]; gs[t] = gam[t]; bts[t] = bet[t]; }
}

// ---------------- 64-row tile MLP (256 threads / 8 warps, all-fp16 single) ----------------
__device__ __forceinline__ void mlp_tile_tc(char* smem, int t) {
    const __half* W1s = (const __half*)(smem + OFF_W1);
    const __half* W2s = (const __half*)(smem + OFF_W2);
    const __half* Xs  = (const __half*)(smem + OFF_X);
    __half* Hs = (__half*)(smem + OFF_H);
    float* Ys = (float*)(smem + OFF_X);   // alias: X dead after GEMM1 sync
    const float* b1s = (const float*)(smem + OFF_B1);
    const float* b2s = (const float*)(smem + OFF_B2);

    const int warp = t >> 5, lane = t & 31;
    const int g = lane >> 2, tg = lane & 3;
    const int m0 = (warp >> 1) * 16;
    const int lrow = lane & 15;
    const int akh  = (lane >> 4) & 1;
    const int brow = lane & 7;
    const int bkh  = (lane >> 3) & 1;
    const int bnt  = (lane >> 4) & 1;

    // ---------------- GEMM1: [64,192]x[192,128], warp tile 16x64 ----------------
    {
        const int n0 = (warp & 1) * 64;
        float C[8][4];
#pragma unroll
        for (int nt = 0; nt < 8; nt++) {
            float bv0 = b1s[n0 + nt * 8 + 2 * tg];
            float bv1 = b1s[n0 + nt * 8 + 2 * tg + 1];
            C[nt][0] = bv0; C[nt][1] = bv1; C[nt][2] = bv0; C[nt][3] = bv1;
        }
        uint32_t aX = smem_u32(Xs + (m0 + lrow) * XS) + akh * 16;
        uint32_t b0a = smem_u32(W1s + (n0 + (0 + bnt) * 8 + brow) * W1S) + bkh * 16;
        uint32_t b1a = smem_u32(W1s + (n0 + (2 + bnt) * 8 + brow) * W1S) + bkh * 16;
        uint32_t b2a = smem_u32(W1s + (n0 + (4 + bnt) * 8 + brow) * W1S) + bkh * 16;
        uint32_t b3a = smem_u32(W1s + (n0 + (6 + bnt) * 8 + brow) * W1S) + bkh * 16;
#pragma unroll
        for (int ks = 0; ks < 12; ks++) {
            const uint32_t off = ks * 32;
            uint32_t a0, a1, a2, a3;
            ldsm4(a0, a1, a2, a3, aX + off);
            uint32_t p0, p1, p2, p3;
            ldsm4(p0, p1, p2, p3, b0a + off);
            uint32_t q0, q1, q2, q3;
            ldsm4(q0, q1, q2, q3, b1a + off);
            mma_fp16(C[0], a0, a1, a2, a3, p0, p1);
            mma_fp16(C[1], a0, a1, a2, a3, p2, p3);
            mma_fp16(C[2], a0, a1, a2, a3, q0, q1);
            mma_fp16(C[3], a0, a1, a2, a3, q2, q3);
            uint32_t r0, r1, r2, r3;
            ldsm4(r0, r1, r2, r3, b2a + off);
            uint32_t s0, s1, s2, s3;
            ldsm4(s0, s1, s2, s3, b3a + off);
            mma_fp16(C[4], a0, a1, a2, a3, r0, r1);
            mma_fp16(C[5], a0, a1, a2, a3, r2, r3);
            mma_fp16(C[6], a0, a1, a2, a3, s0, s1);
            mma_fp16(C[7], a0, a1, a2, a3, s2, s3);
        }
        // GELU -> fp16 H
#pragma unroll
        for (int nt = 0; nt < 8; nt++) {
            const int col = n0 + nt * 8 + 2 * tg;
            float y0 = gelu_f(C[nt][0]);
            float y1 = gelu_f(C[nt][1]);
            float y2 = gelu_f(C[nt][2]);
            float y3 = gelu_f(C[nt][3]);
            *(__half2*)(Hs + (m0 + g) * HS + col)     = __floats2half2_rn(y0, y1);
            *(__half2*)(Hs + (m0 + g + 8) * HS + col) = __floats2half2_rn(y2, y3);
        }
    }
    __syncthreads();   // H complete; X reads done (Y alias safe)

    // ---------------- GEMM2: [64,128]x[128,64], warp tile 16x32 ----------------
    {
        const int n0 = (warp & 1) * 32;
        float C[4][4];
#pragma unroll
        for (int nt = 0; nt < 4; nt++) {
            float bv0 = b2s[n0 + nt * 8 + 2 * tg];
            float bv1 = b2s[n0 + nt * 8 + 2 * tg + 1];
            C[nt][0] = bv0; C[nt][1] = bv1; C[nt][2] = bv0; C[nt][3] = bv1;
        }
        uint32_t aH = smem_u32(Hs + (m0 + lrow) * HS) + akh * 16;
        uint32_t b0a = smem_u32(W2s + (n0 + (0 + bnt) * 8 + brow) * W2S) + bkh * 16;
        uint32_t b1a = smem_u32(W2s + (n0 + (2 + bnt) * 8 + brow) * W2S) + bkh * 16;
#pragma unroll
        for (int ks = 0; ks < 8; ks++) {
            const uint32_t off = ks * 32;
            uint32_t a0, a1, a2, a3;
            ldsm4(a0, a1, a2, a3, aH + off);
            uint32_t p0, p1, p2, p3;
            ldsm4(p0, p1, p2, p3, b0a + off);
            uint32_t q0, q1, q2, q3;
            ldsm4(q0, q1, q2, q3, b1a + off);
            mma_fp16(C[0], a0, a1, a2, a3, p0, p1);
            mma_fp16(C[1], a0, a1, a2, a3, p2, p3);
            mma_fp16(C[2], a0, a1, a2, a3, q0, q1);
            mma_fp16(C[3], a0, a1, a2, a3, q2, q3);
        }
#pragma unroll
        for (int nt = 0; nt < 4; nt++) {
            const int col = n0 + nt * 8 + 2 * tg;
            *(float2*)(Ys + (m0 + g) * YS + col)     = make_float2(C[nt][0], C[nt][1]);
            *(float2*)(Ys + (m0 + g + 8) * YS + col) = make_float2(C[nt][2], C[nt][3]);
        }
    }
    __syncthreads();   // Y visible to LN
}

// ---------------- edge kernel (2 CTAs/SM, register-prefetched gather) ----------------
__global__ __launch_bounds__(256, 2)
void edge_kernel(const float* __restrict__ ndata, const float* __restrict__ edata,
                 const int* __restrict__ src, const int* __restrict__ dst,
                 const float* __restrict__ W1, const float* __restrict__ b1,
                 const float* __restrict__ W2, const float* __restrict__ b2,
                 const float* __restrict__ gam, const float* __restrict__ bet,
                 float* __restrict__ eout, int write_out) {
    extern __shared__ char smem[];
    const int t = threadIdx.x;
    load_weights(smem, W1, b1, W2, b2, gam, bet, t);

    __half* Xs = (__half*)(smem + OFF_X);
    float* Ys  = (float*)(smem + OFF_X);
    const float* gs  = (const float*)(smem + OFF_G);
    const float* bts = (const float*)(smem + OFF_BT);
    int* eidx_base = (int*)(smem + OFF_EIX);   // 2 x 128

    const int numTiles = NE / 64;  // 12500
    const int stride = gridDim.x;
    int tile = blockIdx.x;

    if (t < 128) {
        int e0 = tile * 64;
        eidx_base[t] = (t < 64) ? src[e0 + t] : dst[e0 + (t - 64)];
    }
    __syncthreads();

    // prefetch a tile's gather, converting to fp16 pairs in regs (uint2 per chunk)
    uint2 vals[12];
    auto prefetch = [&](const int* eidx, int e0) {
#pragma unroll
        for (int j = 0; j < 12; j++) {
            int f = t + j * 256;
            int e = f / 48, p = f % 48;
            float4 v;
            if (p < 16)
                v = *(const float4*)(ndata + (size_t)eidx[e] * DD + p * 4);
            else if (p < 32)
                v = *(const float4*)(ndata + (size_t)eidx[64 + e] * DD + (p - 16) * 4);
            else
                v = *(const float4*)(edata + (size_t)(e0 + e) * DD + (p - 32) * 4);
            vals[j].x = pack_h2(v.x, v.y);
            vals[j].y = pack_h2(v.z, v.w);
        }
    };
    auto store_vals = [&]() {
#pragma unroll
        for (int j = 0; j < 12; j++) {
            int f = t + j * 256;
            int e = f / 48, p = f % 48;
            *(uint2*)(Xs + e * XS + p * 4) = vals[j];
        }
    };

    prefetch(eidx_base, tile * 64);
    store_vals();

    int buf = 0;
    for (;;) {
        const int next = tile + stride;
        const bool has_next = next < numTiles;
        const int* eidx_cur = eidx_base + buf * 128;
        int* eidx_nxt = eidx_base + (buf ^ 1) * 128;

        if (has_next && t < 128) {
            int e0n = next * 64;
            eidx_nxt[t] = (t < 64) ? src[e0n + t] : dst[e0n + (t - 64)];
        }
        __syncthreads();   // X stores visible; eidx_nxt visible

        if (has_next) prefetch(eidx_base + (buf ^ 1) * 128, next * 64);

        mlp_tile_tc(smem, t);

        // LayerNorm + output + scatter (8 warps x 8 rows, half-warp per row)
        {
            const int e0 = tile * 64;
            const int warp = t >> 5, lane = t & 31;
            const int half = lane >> 4, l16 = lane & 15;
#pragma unroll
            for (int it = 0; it < 4; ++it) {
                int row = warp * 8 + it * 2 + half;
                float ya[4];
                *(float4*)ya = *(const float4*)(Ys + row * YS + l16 * 4);
                float s  = ya[0] + ya[1] + ya[2] + ya[3];
                float ss = ya[0]*ya[0] + ya[1]*ya[1] + ya[2]*ya[2] + ya[3]*ya[3];
#pragma unroll
                for (int o = 8; o; o >>= 1) {
                    s  += __shfl_xor_sync(0xffffffffu, s, o);
                    ss += __shfl_xor_sync(0xffffffffu, ss, o);
                }
                float mu  = s * (1.0f / 64.0f);
                float var = ss * (1.0f / 64.0f) - mu * mu;
                float rs  = rsqrtf(var + 1e-5f);
                float o4[4];
#pragma unroll
                for (int j = 0; j < 4; j++) {
                    int c = l16 * 4 + j;
                    o4[j] = (ya[j] - mu) * rs * gs[c] + bts[c];
                }
                if (write_out)
                    *(float4*)(eout + (size_t)(e0 + row) * DD + l16 * 4) = *(float4*)o4;
                int sn = eidx_cur[row], dn = eidx_cur[64 + row];
                red_add4(g_sum_src + (size_t)sn * DD + l16 * 4, o4[0], o4[1], o4[2], o4[3]);
                red_add4(g_sum_dst + (size_t)dn * DD + l16 * 4, o4[0], o4[1], o4[2], o4[3]);
                if (l16 == 0) {
                    red_add1(g_cnt_src + sn, 1.0f);
                    red_add1(g_cnt_dst + dn, 1.0f);
                }
            }
        }

        if (!has_next) return;
        __syncthreads();   // Ys (X alias) + eidx_cur consumed

        store_vals();
        buf ^= 1;
        tile = next;
    }
}

// ---------------- node kernel (2 CTAs/SM, pipelined gather) ----------------
__global__ __launch_bounds__(256, 2)
void node_kernel(const float* __restrict__ ndata,
                 const float* __restrict__ W1, const float* __restrict__ b1,
                 const float* __restrict__ W2, const float* __restrict__ b2,
                 const float* __restrict__ gam, const float* __restrict__ bet,
                 float* __restrict__ nout) {
    extern __shared__ char smem[];
    const int t = threadIdx.x;
    load_weights(smem, W1, b1, W2, b2, gam, bet, t);

    __half* Xs = (__half*)(smem + OFF_X);
    float* Ys  = (float*)(smem + OFF_X);
    const float* gs  = (const float*)(smem + OFF_G);
    const float* bts = (const float*)(smem + OFF_BT);

    const int numTiles = (NN + 63) / 64;   // 782
    const int stride = gridDim.x;
    int tile = blockIdx.x;

    uint2 vals[12];
    auto prefetch = [&](int tl) {
#pragma unroll
        for (int j = 0; j < 12; j++) {
            int f = t + j * 256;
            int r = f / 48, p = f % 48;
            int n = tl * 64 + r;
            float4 v = make_float4(0.f, 0.f, 0.f, 0.f);
            if (n < NN) {
                if (p < 16) {
                    float ic = 1.0f / fmaxf(g_cnt_src[n], 1.0f);
                    float4 s4 = *(const float4*)(g_sum_src + (size_t)n * DD + p * 4);
                    v = make_float4(s4.x * ic, s4.y * ic, s4.z * ic, s4.w * ic);
                } else if (p < 32) {
                    float ic = 1.0f / fmaxf(g_cnt_dst[n], 1.0f);
                    float4 s4 = *(const float4*)(g_sum_dst + (size_t)n * DD + (p - 16) * 4);
                    v = make_float4(s4.x * ic, s4.y * ic, s4.z * ic, s4.w * ic);
                } else {
                    v = *(const float4*)(ndata + (size_t)n * DD + (p - 32) * 4);
                }
            }
            vals[j].x = pack_h2(v.x, v.y);
            vals[j].y = pack_h2(v.z, v.w);
        }
    };
    auto store_vals = [&]() {
#pragma unroll
        for (int j = 0; j < 12; j++) {
            int f = t + j * 256;
            int r = f / 48, p = f % 48;
            *(uint2*)(Xs + r * XS + p * 4) = vals[j];
        }
    };

    if (tile < numTiles) {
        prefetch(tile);
        store_vals();
    }

    for (; tile < numTiles; ) {
        __syncthreads();   // X + weights visible

        const int next = tile + stride;
        const bool has_next = next < numTiles;
        if (has_next) prefetch(next);   // overlaps with MMAs

        mlp_tile_tc(smem, t);

        {
            const int n0 = tile * 64;
            const int warp = t >> 5, lane = t & 31;
            const int half = lane >> 4, l16 = lane & 15;
#pragma unroll
            for (int it = 0; it < 4; ++it) {
                int row = warp * 8 + it * 2 + half;
                float ya[4];
                *(float4*)ya = *(const float4*)(Ys + row * YS + l16 * 4);
                float s  = ya[0] + ya[1] + ya[2] + ya[3];
                float ss = ya[0]*ya[0] + ya[1]*ya[1] + ya[2]*ya[2] + ya[3]*ya[3];
#pragma unroll
                for (int o = 8; o; o >>= 1) {
                    s  += __shfl_xor_sync(0xffffffffu, s, o);
                    ss += __shfl_xor_sync(0xffffffffu, ss, o);
                }
                float mu  = s * (1.0f / 64.0f);
                float var = ss * (1.0f / 64.0f) - mu * mu;
                float rs  = rsqrtf(var + 1e-5f);
                int n = n0 + row;
                if (n < NN) {
                    float o4[4];
#pragma unroll
                    for (int j = 0; j < 4; j++) {
                        int c = l16 * 4 + j;
                        o4[j] = (ya[j] - mu) * rs * gs[c] + bts[c];
                    }
                    *(float4*)(nout + (size_t)n * DD + l16 * 4) = *(float4*)o4;
                }
            }
        }

        if (!has_next) break;
        __syncthreads();   // Ys consumed
        store_vals();
        tile = next;
    }
}

// ---------------- launch ----------------
extern "C" void kernel_launch(void* const* d_in, const int* in_sizes, int n_in,
                              void* d_out, int out_size) {
    const float* ndata = (const float*)d_in[0];
    const float* edata = (const float*)d_in[1];
    const int*   src   = (const int*)d_in[2];
    const int*   dst   = (const int*)d_in[3];
    const float* eW1 = (const float*)d_in[4];
    const float* eb1 = (const float*)d_in[5];
    const float* eW2 = (const float*)d_in[6];
    const float* eb2 = (const float*)d_in[7];
    const float* eg  = (const float*)d_in[8];
    const float* ebt = (const float*)d_in[9];
    const float* nW1 = (const float*)d_in[10];
    const float* nb1 = (const float*)d_in[11];
    const float* nW2 = (const float*)d_in[12];
    const float* nb2 = (const float*)d_in[13];
    const float* ng  = (const float*)d_in[14];
    const float* nbt = (const float*)d_in[15];

    float* out  = (float*)d_out;
    float* nout = out;                        // ndata_new first
    float* eout = out + (size_t)NN * DD;      // edata_new second
    int write_edges = (out_size >= (NN + NE) * DD) ? 1 : 0;

    int sm = 148;
    cudaDeviceGetAttribute(&sm, cudaDevAttrMultiProcessorCount, 0);

    cudaFuncSetAttribute(edge_kernel, cudaFuncAttributeMaxDynamicSharedMemorySize, SMEM_BYTES);
    cudaFuncSetAttribute(node_kernel, cudaFuncAttributeMaxDynamicSharedMemorySize, SMEM_BYTES);

    void *p_ss, *p_sd, *p_cs, *p_cd;
    cudaGetSymbolAddress(&p_ss, g_sum_src);
    cudaGetSymbolAddress(&p_sd, g_sum_dst);
    cudaGetSymbolAddress(&p_cs, g_cnt_src);
    cudaGetSymbolAddress(&p_cd, g_cnt_dst);
    cudaMemsetAsync(p_ss, 0, (size_t)NN * DD * sizeof(float), 0);
    cudaMemsetAsync(p_sd, 0, (size_t)NN * DD * sizeof(float), 0);
    cudaMemsetAsync(p_cs, 0, (size_t)NN * sizeof(float), 0);
    cudaMemsetAsync(p_cd, 0, (size_t)NN * sizeof(float), 0);

    edge_kernel<<<2 * sm, 256, SMEM_BYTES>>>(ndata, edata, src, dst,
                                             eW1, eb1, eW2, eb2, eg, ebt,
                                             eout, write_edges);
    node_kernel<<<2 * sm, 256, SMEM_BYTES>>>(ndata, nW1, nb1, nW2, nb2, ng, nbt, nout);
}